// round 16
// baseline (speedup 1.0000x reference)
#include <cuda_runtime.h>
#include <cuda_fp16.h>
#include <math.h>

#define NBATCH 4
#define NC     256
#define HW     65536
#define WIMG   256
#define NSP    1024
#define HID    128
#define ODIM   64
#define INV_T  10.0f

// ---------------- scratch (device globals; no allocation allowed) ----------------
__device__ int    g_cnti[NBATCH * NSP];
__device__ int    g_off[NBATCH * NSP];
__device__ int    g_rank[(size_t)NBATCH * HW];
__device__ unsigned char g_adj[(size_t)NBATCH * NSP * NSP];     // 4 MB
__device__ float  g_invdeg[NBATCH * NSP];
__device__ __half g_featT16[(size_t)NBATCH * HW * NC];          // 128 MB, sorted rows
__device__ __half g_spfh[(size_t)NBATCH * NSP * NC];            // [b][s][c] fp16
__device__ __half g_pT[(size_t)NBATCH * HID * NSP];             // [b][j][s] fp16
__device__ __half g_h1[(size_t)NBATCH * NSP * HID];
__device__ __half g_w1h[HID * NC];
__device__ __half g_w2h[HID * HID];
__device__ __half g_wph[2 * ODIM * HID];                        // Wp1 rows 0-63, Wp2 64-127
__device__ float  g_bp[2 * ODIM];
__device__ __half g_z1h[(size_t)NBATCH * NSP * ODIM];           // normalized z1, fp16
__device__ __half g_z2h[(size_t)NBATCH * NSP * ODIM];           // normalized z2, fp16
__device__ float  g_diag[NBATCH * NSP];

// ---------------- mma helpers ---------------------------------------------------
__device__ __forceinline__ unsigned sptr(const void* p) {
    return (unsigned)__cvta_generic_to_shared(p);
}
__device__ __forceinline__ void ldsm4(unsigned& r0, unsigned& r1, unsigned& r2, unsigned& r3,
                                      unsigned addr) {
    asm volatile("ldmatrix.sync.aligned.m8n8.x4.shared.b16 {%0,%1,%2,%3}, [%4];"
                 : "=r"(r0), "=r"(r1), "=r"(r2), "=r"(r3) : "r"(addr));
}
__device__ __forceinline__ void mma16816(float* d, const unsigned* a, const unsigned* b) {
    asm volatile("mma.sync.aligned.m16n8k16.row.col.f32.f16.f16.f32 "
                 "{%0,%1,%2,%3}, {%4,%5,%6,%7}, {%8,%9}, {%0,%1,%2,%3};"
                 : "+f"(d[0]), "+f"(d[1]), "+f"(d[2]), "+f"(d[3])
                 : "r"(a[0]), "r"(a[1]), "r"(a[2]), "r"(a[3]), "r"(b[0]), "r"(b[1]));
}

// ---------------- prep: zero adj/cnti/out + convert weights + pack biases ------
__global__ __launch_bounds__(256) void prep_kernel(float* d_out,
                                                   const float* __restrict__ W1,
                                                   const float* __restrict__ W2,
                                                   const float* __restrict__ Wp1,
                                                   const float* __restrict__ Wp2,
                                                   const float* __restrict__ bp1,
                                                   const float* __restrict__ bp2) {
    size_t gid = (size_t)blockIdx.x * 256 + threadIdx.x;   // 2048*256
    ((uint2*)g_adj)[gid] = make_uint2(0u, 0u);
    if (gid < (NBATCH * NSP) / 4) ((int4*)g_cnti)[gid] = make_int4(0, 0, 0, 0);
    if (gid == 0) d_out[0] = 0.f;
    int t = (int)gid;
    if (t < 32768)      g_w1h[t] = __float2half(W1[t]);
    else if (t < 49152) g_w2h[t - 32768] = __float2half(W2[t - 32768]);
    else if (t < 57344) g_wph[t - 49152] = __float2half(Wp1[t - 49152]);
    else if (t < 65536) g_wph[t - 49152] = __float2half(Wp2[t - 57344]);
    if (t < ODIM)           g_bp[t] = bp1[t];
    else if (t < 2 * ODIM)  g_bp[t] = bp2[t - ODIM];
}

// ---------------- counts (+rank) + binary adjacency, 4 px/thread ---------------
__global__ __launch_bounds__(256) void count_adj_kernel(const int* __restrict__ idx) {
    int b = blockIdx.y;
    int t = blockIdx.x * 256 + threadIdx.x;      // HW/4 threads
    int p = t * 4;
    const int* ib = idx + (size_t)b * HW;
    int4 s4 = *(const int4*)(ib + p);
    int sNext = (p + 4 < HW) ? ib[p + 4] : 0;
    int4 d4 = make_int4(0, 0, 0, 0);
    if (p < HW - WIMG) d4 = *(const int4*)(ib + p + WIMG);
    int s[5] = {s4.x, s4.y, s4.z, s4.w, sNext};
    int d[4] = {d4.x, d4.y, d4.z, d4.w};
    unsigned char* adjb = g_adj + (size_t)b * NSP * NSP;
    #pragma unroll
    for (int i = 0; i < 4; i++) {
        int si = s[i];
        int r = atomicAdd(&g_cnti[b * NSP + si], 1);
        g_rank[(size_t)b * HW + p + i] = r;
        if (((p + i) & (WIMG - 1)) < WIMG - 1) {
            int s2 = s[i + 1];
            if (s2 != si) { adjb[(size_t)si * NSP + s2] = 1; adjb[(size_t)s2 * NSP + si] = 1; }
        }
        if (p + i < HW - WIMG) {
            int s2 = d[i];
            if (s2 != si) { adjb[(size_t)si * NSP + s2] = 1; adjb[(size_t)s2 * NSP + si] = 1; }
        }
    }
    if (t < NSP) adjb[(size_t)t * NSP + t] = 1;
}

// ---------------- fused: scan (blocks 0-3) + invdeg (blocks 4+) ----------------
__global__ __launch_bounds__(1024) void scan_invdeg_kernel() {
    if (blockIdx.x < NBATCH) {
        __shared__ int sm[NSP];
        int b = blockIdx.x, t = threadIdx.x;
        int v = g_cnti[b * NSP + t];
        sm[t] = v;
        __syncthreads();
        for (int o = 1; o < NSP; o <<= 1) {
            int x = (t >= o) ? sm[t - o] : 0;
            __syncthreads();
            sm[t] += x;
            __syncthreads();
        }
        g_off[b * NSP + t] = sm[t] - v;
    } else {
        int w = threadIdx.x >> 5, lane = threadIdx.x & 31;
        int gr = (blockIdx.x - NBATCH) * 32 + w;   // 0..4095
        int b = gr >> 10, row = gr & (NSP - 1);
        const uint4* r = (const uint4*)(g_adj + ((size_t)b * NSP + row) * NSP);
        uint4 v1 = r[lane], v2 = r[lane + 32];
        unsigned int s = 0u;
        s = __dp4a(v1.x, 0x01010101u, s); s = __dp4a(v1.y, 0x01010101u, s);
        s = __dp4a(v1.z, 0x01010101u, s); s = __dp4a(v1.w, 0x01010101u, s);
        s = __dp4a(v2.x, 0x01010101u, s); s = __dp4a(v2.y, 0x01010101u, s);
        s = __dp4a(v2.z, 0x01010101u, s); s = __dp4a(v2.w, 0x01010101u, s);
        int si = (int)s;
        #pragma unroll
        for (int o = 16; o; o >>= 1) si += __shfl_xor_sync(0xffffffffu, si, o);
        if (lane == 0) g_invdeg[b * NSP + row] = rsqrtf(fmaxf((float)si, 1.0f));
    }
}

// ---------------- scatter-transpose: feat [C,HW] -> featT16 [b][slot][C] -------
__global__ __launch_bounds__(256) void transpose_kernel(const float* __restrict__ feat,
                                                        const int* __restrict__ idx) {
    __shared__ float tile[64][65];
    __shared__ int sl[64];
    int c0 = blockIdx.y * 64, p0 = blockIdx.x * 64, b = blockIdx.z;
    int tid = threadIdx.x;
    if (tid < 64) {
        int p = p0 + tid;
        int s = idx[(size_t)b * HW + p];
        sl[tid] = g_off[b * NSP + s] + g_rank[(size_t)b * HW + p];
    }
    int px = tid & 63, cl = tid >> 6;
    const float* f = feat + ((size_t)b * NC + c0) * HW + p0;
    #pragma unroll
    for (int i = 0; i < 16; i++)
        tile[cl + i * 4][px] = f[(size_t)(cl + i * 4) * HW + px];
    __syncthreads();
    int w = tid >> 5, lane = tid & 31;
    __half2* dst = (__half2*)g_featT16 + (size_t)b * HW * (NC / 2);
    #pragma unroll
    for (int i = 0; i < 8; i++) {
        int p = w + i * 8;
        dst[(size_t)sl[p] * (NC / 2) + (c0 >> 1) + lane] =
            __floats2half2_rn(tile[lane * 2][p], tile[lane * 2 + 1][p]);
    }
}

// ---------------- contiguous segment mean -> spfh [b][s][c] fp16 ---------------
__global__ __launch_bounds__(128) void segsum_kernel() {
    int s = blockIdx.x, b = blockIdx.y, t = threadIdx.x;
    int start = g_off[b * NSP + s];
    int n = g_cnti[b * NSP + s];
    const __half2* base = (const __half2*)g_featT16 +
                          ((size_t)b * HW + start) * (NC / 2) + t;
    float2 a0 = make_float2(0.f, 0.f), a1 = make_float2(0.f, 0.f);
    int r = 0;
    for (; r + 2 <= n; r += 2) {
        float2 x0 = __half22float2(base[(size_t)r * (NC / 2)]);
        float2 x1 = __half22float2(base[(size_t)(r + 1) * (NC / 2)]);
        a0.x += x0.x; a0.y += x0.y; a1.x += x1.x; a1.y += x1.y;
    }
    if (r < n) {
        float2 x0 = __half22float2(base[(size_t)r * (NC / 2)]);
        a0.x += x0.x; a0.y += x0.y;
    }
    float invn = (n > 0) ? 1.f / (float)n : 0.f;
    ((__half2*)g_spfh)[((size_t)b * NSP + s) * (NC / 2) + t] =
        __floats2half2_rn((a0.x + a1.x) * invn, (a0.y + a1.y) * invn);
}

// ---------------- fp16 mma GEMM (used for gemm1 only) ---------------------------
// flags: bit2 transposed fp16 out (C[n][m])
#define GM_BM 64
#define GM_BN 64
#define GM_BK 32
__global__ __launch_bounds__(128) void mma_gemm(
    const __half* __restrict__ A, int lda, size_t sA,
    const __half* __restrict__ B, int ldb, size_t sB,
    void* __restrict__ Cv, int ldc, size_t sC,
    int K, const float* __restrict__ bias, int flags)
{
    __shared__ __half As[GM_BM][GM_BK + 8];
    __shared__ __half Bs[GM_BN][GM_BK + 8];
    int b = blockIdx.z;
    A += (size_t)b * sA;
    B += (size_t)b * sB;
    int m0 = blockIdx.y * GM_BM, n0 = blockIdx.x * GM_BN;
    int tid = threadIdx.x, w = tid >> 5, lane = tid & 31;
    int wm = (w >> 1) * 32, wn = (w & 1) * 32;
    float acc[2][4][4];
    #pragma unroll
    for (int i = 0; i < 2; i++)
        #pragma unroll
        for (int j = 0; j < 4; j++)
            #pragma unroll
            for (int q = 0; q < 4; q++) acc[i][j][q] = 0.f;

    int r8 = lane & 7, grp = lane >> 3;
    for (int k0 = 0; k0 < K; k0 += GM_BK) {
        int rr = tid >> 1, oo = (tid & 1) * 16;
        {
            const __half* pa = A + (size_t)(m0 + rr) * lda + k0 + oo;
            *(uint4*)&As[rr][oo]     = *(const uint4*)pa;
            *(uint4*)&As[rr][oo + 8] = *(const uint4*)(pa + 8);
            const __half* pb = B + (size_t)(n0 + rr) * ldb + k0 + oo;
            *(uint4*)&Bs[rr][oo]     = *(const uint4*)pb;
            *(uint4*)&Bs[rr][oo + 8] = *(const uint4*)(pb + 8);
        }
        __syncthreads();
        #pragma unroll
        for (int kk = 0; kk < GM_BK; kk += 16) {
            unsigned af[2][4], bf[4][2];
            #pragma unroll
            for (int i = 0; i < 2; i++) {
                unsigned ad = sptr(&As[wm + i * 16 + r8 + ((grp & 1) << 3)][kk + ((grp & 2) << 2)]);
                ldsm4(af[i][0], af[i][1], af[i][2], af[i][3], ad);
            }
            #pragma unroll
            for (int jp = 0; jp < 2; jp++) {
                unsigned q0, q1, q2, q3;
                unsigned ad = sptr(&Bs[wn + jp * 16 + r8 + ((grp & 2) << 2)][kk + ((grp & 1) << 3)]);
                ldsm4(q0, q1, q2, q3, ad);
                bf[jp * 2][0] = q0;     bf[jp * 2][1] = q1;
                bf[jp * 2 + 1][0] = q2; bf[jp * 2 + 1][1] = q3;
            }
            #pragma unroll
            for (int i = 0; i < 2; i++)
                #pragma unroll
                for (int j = 0; j < 4; j++) mma16816(acc[i][j], af[i], bf[j]);
        }
        __syncthreads();
    }
    int rr = lane >> 2, cg = (lane & 3) * 2;
    #pragma unroll
    for (int i = 0; i < 2; i++) {
        int gm = m0 + wm + i * 16 + rr;
        #pragma unroll
        for (int j = 0; j < 4; j++) {
            int gn = n0 + wn + j * 8 + cg;
            float v0 = acc[i][j][0], v1 = acc[i][j][1];
            float v2 = acc[i][j][2], v3 = acc[i][j][3];
            if (flags & 4) {                       // transposed fp16 out: C[n][m]
                __half* C = (__half*)Cv + (size_t)b * sC;
                C[(size_t)gn * ldc + gm]           = __float2half(v0);
                C[(size_t)(gn + 1) * ldc + gm]     = __float2half(v1);
                C[(size_t)gn * ldc + gm + 8]       = __float2half(v2);
                C[(size_t)(gn + 1) * ldc + gm + 8] = __float2half(v3);
            } else {
                __half* C = (__half*)Cv + (size_t)b * sC;
                *(__half2*)(C + (size_t)gm * ldc + gn) = __floats2half2_rn(v0, v1);
                *(__half2*)(C + (size_t)(gm + 8) * ldc + gn) = __floats2half2_rn(v2, v3);
            }
        }
    }
}

// ---------------- adjacency GEMM: h1 = relu(D^-1/2 A D^-1/2 @ p + b1) ----------
__global__ __launch_bounds__(128) void adj_gemm(const float* __restrict__ bias) {
    __shared__ __half As[GM_BM][GM_BK + 8];
    __shared__ __half Bs[GM_BN][GM_BK + 8];
    __shared__ float sInv[NSP];
    int b = blockIdx.z;
    const unsigned char* A8 = g_adj + (size_t)b * NSP * NSP;
    const __half* B = g_pT + (size_t)b * HID * NSP;
    __half* C = g_h1 + (size_t)b * NSP * HID;
    int m0 = blockIdx.y * GM_BM, n0 = blockIdx.x * GM_BN;
    int tid = threadIdx.x, w = tid >> 5, lane = tid & 31;
    int wm = (w >> 1) * 32, wn = (w & 1) * 32;
    #pragma unroll
    for (int i = 0; i < NSP / 128; i++)
        sInv[tid + i * 128] = g_invdeg[b * NSP + tid + i * 128];
    __syncthreads();

    float acc[2][4][4];
    #pragma unroll
    for (int i = 0; i < 2; i++)
        #pragma unroll
        for (int j = 0; j < 4; j++)
            #pragma unroll
            for (int q = 0; q < 4; q++) acc[i][j][q] = 0.f;

    int r8 = lane & 7, grp = lane >> 3;
    for (int k0 = 0; k0 < NSP; k0 += GM_BK) {
        int rr = tid >> 1, oo = (tid & 1) * 16;
        {
            float im = sInv[m0 + rr];
            const unsigned* pa = (const unsigned*)(A8 + (size_t)(m0 + rr) * NSP + k0 + oo);
            __half hbuf[16];
            #pragma unroll
            for (int q = 0; q < 4; q++) {
                unsigned v = pa[q];
                #pragma unroll
                for (int e = 0; e < 4; e++) {
                    unsigned byte = (v >> (8 * e)) & 0xffu;
                    int kidx = k0 + oo + q * 4 + e;
                    hbuf[q * 4 + e] = byte ? __float2half(im * sInv[kidx]) : __half(0);
                }
            }
            *(uint4*)&As[rr][oo]     = *(uint4*)&hbuf[0];
            *(uint4*)&As[rr][oo + 8] = *(uint4*)&hbuf[8];
            const __half* pb = B + (size_t)(n0 + rr) * NSP + k0 + oo;
            *(uint4*)&Bs[rr][oo]     = *(const uint4*)pb;
            *(uint4*)&Bs[rr][oo + 8] = *(const uint4*)(pb + 8);
        }
        __syncthreads();
        #pragma unroll
        for (int kk = 0; kk < GM_BK; kk += 16) {
            unsigned af[2][4], bf[4][2];
            #pragma unroll
            for (int i = 0; i < 2; i++) {
                unsigned ad = sptr(&As[wm + i * 16 + r8 + ((grp & 1) << 3)][kk + ((grp & 2) << 2)]);
                ldsm4(af[i][0], af[i][1], af[i][2], af[i][3], ad);
            }
            #pragma unroll
            for (int jp = 0; jp < 2; jp++) {
                unsigned q0, q1, q2, q3;
                unsigned ad = sptr(&Bs[wn + jp * 16 + r8 + ((grp & 2) << 2)][kk + ((grp & 1) << 3)]);
                ldsm4(q0, q1, q2, q3, ad);
                bf[jp * 2][0] = q0;     bf[jp * 2][1] = q1;
                bf[jp * 2 + 1][0] = q2; bf[jp * 2 + 1][1] = q3;
            }
            #pragma unroll
            for (int i = 0; i < 2; i++)
                #pragma unroll
                for (int j = 0; j < 4; j++) mma16816(acc[i][j], af[i], bf[j]);
        }
        __syncthreads();
    }
    int rr = lane >> 2, cg = (lane & 3) * 2;
    #pragma unroll
    for (int i = 0; i < 2; i++) {
        int gm = m0 + wm + i * 16 + rr;
        #pragma unroll
        for (int j = 0; j < 4; j++) {
            int gn = n0 + wn + j * 8 + cg;
            float bx = bias[gn], by = bias[gn + 1];
            float v0 = fmaxf(acc[i][j][0] + bx, 0.f);
            float v1 = fmaxf(acc[i][j][1] + by, 0.f);
            float v2 = fmaxf(acc[i][j][2] + bx, 0.f);
            float v3 = fmaxf(acc[i][j][3] + by, 0.f);
            *(__half2*)(C + (size_t)gm * HID + gn) = __floats2half2_rn(v0, v1);
            *(__half2*)(C + (size_t)(gm + 8) * HID + gn) = __floats2half2_rn(v2, v3);
        }
    }
}

// ---------------- fused MLP: h2 = relu(h1@W2^T+b2); z = h2@Wp^T+bp; normalize --
// Block: 64 s-rows x full 128 cols, 128 threads. Outputs z1h/z2h fp16 + diag.
// smem union: phase [As 64x40 | Bs 128x40 | H 64x136] ; epi [Z 64x132 fp32]
__global__ __launch_bounds__(128) void mlp_kernel(const float* __restrict__ b2) {
    __shared__ __align__(16) unsigned char smraw[33792];
    __half (*As)[40]  = (__half(*)[40])smraw;                    // 5120 B
    __half (*Bs)[40]  = (__half(*)[40])(smraw + 5120);           // 10240 B
    __half (*H)[136]  = (__half(*)[136])(smraw + 15360);         // 17408 B
    float  (*Z)[132]  = (float(*)[132])smraw;                    // 33792 B (aliases all)
    int b = blockIdx.y, m0 = blockIdx.x * 64;
    int tid = threadIdx.x, w = tid >> 5, lane = tid & 31;
    int wm = (w >> 1) * 32, wn = (w & 1) * 64;
    int r8 = lane & 7, grp = lane >> 3;
    int rr2 = lane >> 2, cg = (lane & 3) * 2;
    const __half* A = g_h1 + (size_t)b * NSP * HID;

    // ---- phase 1: h2 tile = relu(h1 @ W2^T + b2) -> H smem
    {
        float acc[2][8][4];
        #pragma unroll
        for (int i = 0; i < 2; i++)
            #pragma unroll
            for (int j = 0; j < 8; j++)
                #pragma unroll
                for (int q = 0; q < 4; q++) acc[i][j][q] = 0.f;
        for (int k0 = 0; k0 < HID; k0 += 32) {
            {
                int rr = tid >> 1, oo = (tid & 1) * 16;
                const __half* pa = A + (size_t)(m0 + rr) * HID + k0 + oo;
                *(uint4*)&As[rr][oo]     = *(const uint4*)pa;
                *(uint4*)&As[rr][oo + 8] = *(const uint4*)(pa + 8);
                const __half* pb = g_w2h + (size_t)tid * HID + k0;
                *(uint4*)&Bs[tid][0]  = *(const uint4*)pb;
                *(uint4*)&Bs[tid][8]  = *(const uint4*)(pb + 8);
                *(uint4*)&Bs[tid][16] = *(const uint4*)(pb + 16);
                *(uint4*)&Bs[tid][24] = *(const uint4*)(pb + 24);
            }
            __syncthreads();
            #pragma unroll
            for (int kk = 0; kk < 32; kk += 16) {
                unsigned af[2][4], bf[8][2];
                #pragma unroll
                for (int i = 0; i < 2; i++) {
                    unsigned ad = sptr(&As[wm + i * 16 + r8 + ((grp & 1) << 3)][kk + ((grp & 2) << 2)]);
                    ldsm4(af[i][0], af[i][1], af[i][2], af[i][3], ad);
                }
                #pragma unroll
                for (int jp = 0; jp < 4; jp++) {
                    unsigned q0, q1, q2, q3;
                    unsigned ad = sptr(&Bs[wn + jp * 16 + r8 + ((grp & 2) << 2)][kk + ((grp & 1) << 3)]);
                    ldsm4(q0, q1, q2, q3, ad);
                    bf[jp * 2][0] = q0;     bf[jp * 2][1] = q1;
                    bf[jp * 2 + 1][0] = q2; bf[jp * 2 + 1][1] = q3;
                }
                #pragma unroll
                for (int i = 0; i < 2; i++)
                    #pragma unroll
                    for (int j = 0; j < 8; j++) mma16816(acc[i][j], af[i], bf[j]);
            }
            __syncthreads();
        }
        #pragma unroll
        for (int i = 0; i < 2; i++) {
            int gm = wm + i * 16 + rr2;
            #pragma unroll
            for (int j = 0; j < 8; j++) {
                int gn = wn + j * 8 + cg;
                float bx = b2[gn], by = b2[gn + 1];
                *(__half2*)&H[gm][gn] = __floats2half2_rn(
                    fmaxf(acc[i][j][0] + bx, 0.f), fmaxf(acc[i][j][1] + by, 0.f));
                *(__half2*)&H[gm + 8][gn] = __floats2half2_rn(
                    fmaxf(acc[i][j][2] + bx, 0.f), fmaxf(acc[i][j][3] + by, 0.f));
            }
        }
    }
    __syncthreads();
    // ---- phase 2: z tile = H @ Wph^T + bp -> Z smem (fp32)
    {
        float acc[2][8][4];
        #pragma unroll
        for (int i = 0; i < 2; i++)
            #pragma unroll
            for (int j = 0; j < 8; j++)
                #pragma unroll
                for (int q = 0; q < 4; q++) acc[i][j][q] = 0.f;
        for (int k0 = 0; k0 < HID; k0 += 32) {
            {
                const __half* pb = g_wph + (size_t)tid * HID + k0;
                *(uint4*)&Bs[tid][0]  = *(const uint4*)pb;
                *(uint4*)&Bs[tid][8]  = *(const uint4*)(pb + 8);
                *(uint4*)&Bs[tid][16] = *(const uint4*)(pb + 16);
                *(uint4*)&Bs[tid][24] = *(const uint4*)(pb + 24);
            }
            __syncthreads();
            #pragma unroll
            for (int kk = 0; kk < 32; kk += 16) {
                unsigned af[2][4], bf[8][2];
                #pragma unroll
                for (int i = 0; i < 2; i++) {
                    unsigned ad = sptr(&H[wm + i * 16 + r8 + ((grp & 1) << 3)][k0 + kk + ((grp & 2) << 2)]);
                    ldsm4(af[i][0], af[i][1], af[i][2], af[i][3], ad);
                }
                #pragma unroll
                for (int jp = 0; jp < 4; jp++) {
                    unsigned q0, q1, q2, q3;
                    unsigned ad = sptr(&Bs[wn + jp * 16 + r8 + ((grp & 2) << 2)][kk + ((grp & 1) << 3)]);
                    ldsm4(q0, q1, q2, q3, ad);
                    bf[jp * 2][0] = q0;     bf[jp * 2][1] = q1;
                    bf[jp * 2 + 1][0] = q2; bf[jp * 2 + 1][1] = q3;
                }
                #pragma unroll
                for (int i = 0; i < 2; i++)
                    #pragma unroll
                    for (int j = 0; j < 8; j++) mma16816(acc[i][j], af[i], bf[j]);
            }
            __syncthreads();
        }
        // write Z (aliases As/Bs/H — all dead after the sync above)
        #pragma unroll
        for (int i = 0; i < 2; i++) {
            int gm = wm + i * 16 + rr2;
            #pragma unroll
            for (int j = 0; j < 8; j++) {
                int gn = wn + j * 8 + cg;
                float bx = g_bp[gn], by = g_bp[gn + 1];
                Z[gm][gn]         = acc[i][j][0] + bx;
                Z[gm][gn + 1]     = acc[i][j][1] + by;
                Z[gm + 8][gn]     = acc[i][j][2] + bx;
                Z[gm + 8][gn + 1] = acc[i][j][3] + by;
            }
        }
    }
    __syncthreads();
    // ---- normalize rows, emit fp16 z1h/z2h + fp32 diag
    for (int r = 0; r < 16; r++) {
        int row = w * 16 + r;
        float a0 = Z[row][lane], a1 = Z[row][lane + 32];
        float ss = a0 * a0 + a1 * a1;
        #pragma unroll
        for (int o = 16; o; o >>= 1) ss += __shfl_xor_sync(0xffffffffu, ss, o);
        float inv = rsqrtf(fmaxf(ss, 1e-30f));
        float a0n = a0 * inv, a1n = a1 * inv;
        float c0 = Z[row][64 + lane], c1 = Z[row][96 + lane];
        float ss2 = c0 * c0 + c1 * c1;
        #pragma unroll
        for (int o = 16; o; o >>= 1) ss2 += __shfl_xor_sync(0xffffffffu, ss2, o);
        float inv2 = rsqrtf(fmaxf(ss2, 1e-30f));
        float c0n = c0 * inv2, c1n = c1 * inv2;
        size_t base = ((size_t)b * NSP + m0 + row) * ODIM;
        g_z1h[base + lane]      = __float2half(a0n);
        g_z1h[base + lane + 32] = __float2half(a1n);
        g_z2h[base + lane]      = __float2half(c0n);
        g_z2h[base + lane + 32] = __float2half(c1n);
        float dd = a0n * c0n + a1n * c1n;
        #pragma unroll
        for (int o = 16; o; o >>= 1) dd += __shfl_xor_sync(0xffffffffu, dd, o);
        if (lane == 0) g_diag[b * NSP + m0 + row] = dd * INV_T;
    }
}

// ---------------- tensor-core sim + online logsumexp + loss --------------------
// Block: 64 m-rows, sweep all 1024 n in 64-chunks. 128 threads.
__global__ __launch_bounds__(128) void simlse_kernel(float* __restrict__ out) {
    __shared__ __half As[64][72];
    __shared__ __half Bs[64][72];
    __shared__ float pm[64][2], ps[64][2], sloss[64];
    int b = blockIdx.y, m0 = blockIdx.x * 64;
    int tid = threadIdx.x, w = tid >> 5, lane = tid & 31;
    int wm = (w >> 1) * 32, wn = (w & 1) * 32;
    int r8 = lane & 7, grp = lane >> 3;
    const __half* z1 = g_z1h + (size_t)b * NSP * ODIM;
    const __half* z2 = g_z2h + (size_t)b * NSP * ODIM;
    {
        int rr = tid >> 1, oo = (tid & 1) * 32;
        const __half* pa = z1 + (size_t)(m0 + rr) * ODIM + oo;
        *(uint4*)&As[rr][oo]      = *(const uint4*)pa;
        *(uint4*)&As[rr][oo + 8]  = *(const uint4*)(pa + 8);
        *(uint4*)&As[rr][oo + 16] = *(const uint4*)(pa + 16);
        *(uint4*)&As[rr][oo + 24] = *(const uint4*)(pa + 24);
    }
    float mrun[4], srun[4];
    #pragma unroll
    for (int i = 0; i < 4; i++) { mrun[i] = -1e30f; srun[i] = 0.f; }

    for (int n0 = 0; n0 < NSP; n0 += 64) {
        {
            int rr = tid >> 1, oo = (tid & 1) * 32;
            const __half* pb = z2 + (size_t)(n0 + rr) * ODIM + oo;
            *(uint4*)&Bs[rr][oo]      = *(const uint4*)pb;
            *(uint4*)&Bs[rr][oo + 8]  = *(const uint4*)(pb + 8);
            *(uint4*)&Bs[rr][oo + 16] = *(const uint4*)(pb + 16);
            *(uint4*)&Bs[rr][oo + 24] = *(const uint4*)(pb + 24);
        }
        __syncthreads();
        float acc[2][4][4];
        #pragma unroll
        for (int i = 0; i < 2; i++)
            #pragma unroll
            for (int j = 0; j < 4; j++)
                #pragma unroll
                for (int q = 0; q < 4; q++) acc[i][j][q] = 0.f;
        #pragma unroll
        for (int kk = 0; kk < ODIM; kk += 16) {
            unsigned af[2][4], bf[4][2];
            #pragma unroll
            for (int i = 0; i < 2; i++) {
                unsigned ad = sptr(&As[wm + i * 16 + r8 + ((grp & 1) << 3)][kk + ((grp & 2) << 2)]);
                ldsm4(af[i][0], af[i][1], af[i][2], af[i][3], ad);
            }
            #pragma unroll
            for (int jp = 0; jp < 2; jp++) {
                unsigned q0, q1, q2, q3;
                unsigned ad = sptr(&Bs[wn + jp * 16 + r8 + ((grp & 2) << 2)][kk + ((grp & 1) << 3)]);
                ldsm4(q0, q1, q2, q3, ad);
                bf[jp * 2][0] = q0;     bf[jp * 2][1] = q1;
                bf[jp * 2 + 1][0] = q2; bf[jp * 2 + 1][1] = q3;
            }
            #pragma unroll
            for (int i = 0; i < 2; i++)
                #pragma unroll
                for (int j = 0; j < 4; j++) mma16816(acc[i][j], af[i], bf[j]);
        }
        // online lse update: slot = i*2 + (q>>1)  (rows wm+i*16+rr2 and +8)
        #pragma unroll
        for (int i = 0; i < 2; i++)
            #pragma unroll
            for (int j = 0; j < 4; j++)
                #pragma unroll
                for (int q = 0; q < 4; q++) {
                    float v = acc[i][j][q] * INV_T;
                    int slot = i * 2 + (q >> 1);
                    if (v > mrun[slot]) {
                        srun[slot] = srun[slot] * __expf(mrun[slot] - v) + 1.f;
                        mrun[slot] = v;
                    } else {
                        srun[slot] += __expf(v - mrun[slot]);
                    }
                }
        __syncthreads();
    }
    // combine 4 lanes sharing each row (lane&3), then cross-warp via smem
    int rr2 = lane >> 2;
    #pragma unroll
    for (int slot = 0; slot < 4; slot++) {
        float m = mrun[slot], s = srun[slot];
        #pragma unroll
        for (int off = 1; off < 4; off <<= 1) {
            float m2 = __shfl_xor_sync(0xffffffffu, m, off);
            float s2 = __shfl_xor_sync(0xffffffffu, s, off);
            float mn = fmaxf(m, m2);
            s = s * __expf(m - mn) + s2 * __expf(m2 - mn);
            m = mn;
        }
        if ((lane & 3) == 0) {
            int row = wm + (slot >> 1) * 16 + rr2 + (slot & 1) * 8;
            pm[row][w & 1] = m;
            ps[row][w & 1] = s;
        }
    }
    __syncthreads();
    if (tid < 64) {
        float m0v = pm[tid][0], m1v = pm[tid][1];
        float mn = fmaxf(m0v, m1v);
        float s = ps[tid][0] * __expf(m0v - mn) + ps[tid][1] * __expf(m1v - mn);
        float lse = mn + logf(s);
        sloss[tid] = lse - g_diag[b * NSP + m0 + tid];
    }
    __syncthreads();
    if (tid == 0) {
        float sum = 0.f;
        #pragma unroll
        for (int i = 0; i < 64; i++) sum += sloss[i];
        atomicAdd(out, sum * (1.0f / (NBATCH * NSP)));
    }
}

// ---------------- host launcher -----------------------------------------------
static void* dvp(const void* sym) {
    void* p = nullptr;
    cudaGetSymbolAddress(&p, sym);
    return p;
}

extern "C" void kernel_launch(void* const* d_in, const int* in_sizes, int n_in,
                              void* d_out, int out_size) {
    const float* features = (const float*)d_in[0];
    const int*   spidx    = (const int*)d_in[1];
    const float* W1  = (const float*)d_in[2];
    const float* b1  = (const float*)d_in[3];
    const float* W2  = (const float*)d_in[4];
    const float* b2  = (const float*)d_in[5];
    const float* Wp1 = (const float*)d_in[6];
    const float* bp1 = (const float*)d_in[7];
    const float* Wp2 = (const float*)d_in[8];
    const float* bp2 = (const float*)d_in[9];
    float* out = (float*)d_out;

    __half* p_spfh = (__half*)dvp(g_spfh);
    __half* p_pT   = (__half*)dvp(g_pT);
    __half* p_w1h  = (__half*)dvp(g_w1h);

    prep_kernel<<<2048, 256>>>(out, W1, W2, Wp1, Wp2, bp1, bp2);
    count_adj_kernel<<<dim3(HW / 1024, NBATCH), 256>>>(spidx);
    scan_invdeg_kernel<<<NBATCH + (NBATCH * NSP) / 32, 1024>>>();
    transpose_kernel<<<dim3(HW / 64, NC / 64, NBATCH), 256>>>(features, spidx);
    segsum_kernel<<<dim3(NSP, NBATCH), 128>>>();
    // gemm1: pT[j][s] = (spfh @ W1^T)^T   (transposed fp16 out)
    mma_gemm<<<dim3(HID / GM_BN, NSP / GM_BM, NBATCH), 128>>>(
        p_spfh, NC, (size_t)NSP * NC,
        p_w1h, NC, 0,
        p_pT, NSP, (size_t)HID * NSP,
        NC, nullptr, 4);
    // gemm2: h1 = relu(adj_norm @ p + b1)
    adj_gemm<<<dim3(HID / GM_BN, NSP / GM_BM, NBATCH), 128>>>(b1);
    // fused mlp: h2, projections, row-normalize -> z1h/z2h/diag
    mlp_kernel<<<dim3(NSP / 64, NBATCH), 128>>>(b2);
    // fused tensor-core sim + lse + loss
    simlse_kernel<<<dim3(NSP / 64, NBATCH), 128>>>(out);
}

// round 17
// speedup vs baseline: 1.0205x; 1.0205x over previous
#include <cuda_runtime.h>
#include <cuda_fp16.h>
#include <math.h>

#define NBATCH 4
#define NC     256
#define HW     65536
#define WIMG   256
#define NSP    1024
#define HID    128
#define ODIM   64
#define INV_T  10.0f

// ---------------- scratch (device globals; no allocation allowed) ----------------
__device__ int    g_cnti[NBATCH * NSP];
__device__ int    g_off[NBATCH * NSP];
__device__ int    g_rank[(size_t)NBATCH * HW];
__device__ unsigned char g_adj[(size_t)NBATCH * NSP * NSP];     // 4 MB
__device__ float  g_invdeg[NBATCH * NSP];
__device__ __half g_featT16[(size_t)NBATCH * HW * NC];          // 128 MB, sorted rows
__device__ __half g_spfh[(size_t)NBATCH * NSP * NC];            // [b][s][c] fp16
__device__ __half g_pT[(size_t)NBATCH * HID * NSP];             // [b][j][s] fp16
__device__ __half g_h1[(size_t)NBATCH * NSP * HID];
__device__ __half g_w1h[HID * NC];
__device__ __half g_w2h[HID * HID];
__device__ __half g_wph[2 * ODIM * HID];                        // Wp1 rows 0-63, Wp2 64-127
__device__ float  g_bp[2 * ODIM];
__device__ __half g_z1h[(size_t)NBATCH * NSP * ODIM];           // normalized z1, fp16
__device__ __half g_z2h[(size_t)NBATCH * NSP * ODIM];           // normalized z2, fp16
__device__ float  g_diag[NBATCH * NSP];

// ---------------- mma helpers ---------------------------------------------------
__device__ __forceinline__ unsigned sptr(const void* p) {
    return (unsigned)__cvta_generic_to_shared(p);
}
__device__ __forceinline__ void ldsm4(unsigned& r0, unsigned& r1, unsigned& r2, unsigned& r3,
                                      unsigned addr) {
    asm volatile("ldmatrix.sync.aligned.m8n8.x4.shared.b16 {%0,%1,%2,%3}, [%4];"
                 : "=r"(r0), "=r"(r1), "=r"(r2), "=r"(r3) : "r"(addr));
}
__device__ __forceinline__ void mma16816(float* d, const unsigned* a, const unsigned* b) {
    asm volatile("mma.sync.aligned.m16n8k16.row.col.f32.f16.f16.f32 "
                 "{%0,%1,%2,%3}, {%4,%5,%6,%7}, {%8,%9}, {%0,%1,%2,%3};"
                 : "+f"(d[0]), "+f"(d[1]), "+f"(d[2]), "+f"(d[3])
                 : "r"(a[0]), "r"(a[1]), "r"(a[2]), "r"(a[3]), "r"(b[0]), "r"(b[1]));
}

// ---------------- prep: zero adj/cnti/out + convert weights + pack biases ------
__global__ __launch_bounds__(256) void prep_kernel(float* d_out,
                                                   const float* __restrict__ W1,
                                                   const float* __restrict__ W2,
                                                   const float* __restrict__ Wp1,
                                                   const float* __restrict__ Wp2,
                                                   const float* __restrict__ bp1,
                                                   const float* __restrict__ bp2) {
    size_t gid = (size_t)blockIdx.x * 256 + threadIdx.x;   // 2048*256
    ((uint2*)g_adj)[gid] = make_uint2(0u, 0u);
    if (gid < (NBATCH * NSP) / 4) ((int4*)g_cnti)[gid] = make_int4(0, 0, 0, 0);
    if (gid == 0) d_out[0] = 0.f;
    int t = (int)gid;
    if (t < 32768)      g_w1h[t] = __float2half(W1[t]);
    else if (t < 49152) g_w2h[t - 32768] = __float2half(W2[t - 32768]);
    else if (t < 57344) g_wph[t - 49152] = __float2half(Wp1[t - 49152]);
    else if (t < 65536) g_wph[t - 49152] = __float2half(Wp2[t - 57344]);
    if (t < ODIM)           g_bp[t] = bp1[t];
    else if (t < 2 * ODIM)  g_bp[t] = bp2[t - ODIM];
}

// ---------------- counts (+rank) + binary adjacency, 4 px/thread ---------------
__global__ __launch_bounds__(256) void count_adj_kernel(const int* __restrict__ idx) {
    int b = blockIdx.y;
    int t = blockIdx.x * 256 + threadIdx.x;      // HW/4 threads
    int p = t * 4;
    const int* ib = idx + (size_t)b * HW;
    int4 s4 = *(const int4*)(ib + p);
    int sNext = (p + 4 < HW) ? ib[p + 4] : 0;
    int4 d4 = make_int4(0, 0, 0, 0);
    if (p < HW - WIMG) d4 = *(const int4*)(ib + p + WIMG);
    int s[5] = {s4.x, s4.y, s4.z, s4.w, sNext};
    int d[4] = {d4.x, d4.y, d4.z, d4.w};
    unsigned char* adjb = g_adj + (size_t)b * NSP * NSP;
    #pragma unroll
    for (int i = 0; i < 4; i++) {
        int si = s[i];
        int r = atomicAdd(&g_cnti[b * NSP + si], 1);
        g_rank[(size_t)b * HW + p + i] = r;
        if (((p + i) & (WIMG - 1)) < WIMG - 1) {
            int s2 = s[i + 1];
            if (s2 != si) { adjb[(size_t)si * NSP + s2] = 1; adjb[(size_t)s2 * NSP + si] = 1; }
        }
        if (p + i < HW - WIMG) {
            int s2 = d[i];
            if (s2 != si) { adjb[(size_t)si * NSP + s2] = 1; adjb[(size_t)s2 * NSP + si] = 1; }
        }
    }
    if (t < NSP) adjb[(size_t)t * NSP + t] = 1;
}

// ---------------- fused: scan (blocks 0-3) + invdeg (blocks 4+) ----------------
__global__ __launch_bounds__(1024) void scan_invdeg_kernel() {
    if (blockIdx.x < NBATCH) {
        __shared__ int sm[NSP];
        int b = blockIdx.x, t = threadIdx.x;
        int v = g_cnti[b * NSP + t];
        sm[t] = v;
        __syncthreads();
        for (int o = 1; o < NSP; o <<= 1) {
            int x = (t >= o) ? sm[t - o] : 0;
            __syncthreads();
            sm[t] += x;
            __syncthreads();
        }
        g_off[b * NSP + t] = sm[t] - v;
    } else {
        int w = threadIdx.x >> 5, lane = threadIdx.x & 31;
        int gr = (blockIdx.x - NBATCH) * 32 + w;   // 0..4095
        int b = gr >> 10, row = gr & (NSP - 1);
        const uint4* r = (const uint4*)(g_adj + ((size_t)b * NSP + row) * NSP);
        uint4 v1 = r[lane], v2 = r[lane + 32];
        unsigned int s = 0u;
        s = __dp4a(v1.x, 0x01010101u, s); s = __dp4a(v1.y, 0x01010101u, s);
        s = __dp4a(v1.z, 0x01010101u, s); s = __dp4a(v1.w, 0x01010101u, s);
        s = __dp4a(v2.x, 0x01010101u, s); s = __dp4a(v2.y, 0x01010101u, s);
        s = __dp4a(v2.z, 0x01010101u, s); s = __dp4a(v2.w, 0x01010101u, s);
        int si = (int)s;
        #pragma unroll
        for (int o = 16; o; o >>= 1) si += __shfl_xor_sync(0xffffffffu, si, o);
        if (lane == 0) g_invdeg[b * NSP + row] = rsqrtf(fmaxf((float)si, 1.0f));
    }
}

// ---------------- scatter-transpose: feat [C,HW] -> featT16 [b][slot][C] -------
// Feature reads use __ldcs (evict-first) so the streamed 256 MB does NOT evict
// the 128 MB featT16 being written — keeping it L2-resident for segsum.
__global__ __launch_bounds__(256) void transpose_kernel(const float* __restrict__ feat,
                                                        const int* __restrict__ idx) {
    __shared__ float tile[64][65];
    __shared__ int sl[64];
    int c0 = blockIdx.y * 64, p0 = blockIdx.x * 64, b = blockIdx.z;
    int tid = threadIdx.x;
    if (tid < 64) {
        int p = p0 + tid;
        int s = idx[(size_t)b * HW + p];
        sl[tid] = g_off[b * NSP + s] + g_rank[(size_t)b * HW + p];
    }
    int px = tid & 63, cl = tid >> 6;
    const float* f = feat + ((size_t)b * NC + c0) * HW + p0;
    #pragma unroll
    for (int i = 0; i < 16; i++)
        tile[cl + i * 4][px] = __ldcs(&f[(size_t)(cl + i * 4) * HW + px]);
    __syncthreads();
    int w = tid >> 5, lane = tid & 31;
    __half2* dst = (__half2*)g_featT16 + (size_t)b * HW * (NC / 2);
    #pragma unroll
    for (int i = 0; i < 8; i++) {
        int p = w + i * 8;
        dst[(size_t)sl[p] * (NC / 2) + (c0 >> 1) + lane] =
            __floats2half2_rn(tile[lane * 2][p], tile[lane * 2 + 1][p]);
    }
}

// ---------------- contiguous segment mean -> spfh [b][s][c] fp16 ---------------
// featT16 reads are single-use: __ldcs keeps them from polluting L2 further.
__global__ __launch_bounds__(128) void segsum_kernel() {
    int s = blockIdx.x, b = blockIdx.y, t = threadIdx.x;
    int start = g_off[b * NSP + s];
    int n = g_cnti[b * NSP + s];
    const __half2* base = (const __half2*)g_featT16 +
                          ((size_t)b * HW + start) * (NC / 2) + t;
    float2 a0 = make_float2(0.f, 0.f), a1 = make_float2(0.f, 0.f);
    float2 a2 = make_float2(0.f, 0.f), a3 = make_float2(0.f, 0.f);
    int r = 0;
    for (; r + 4 <= n; r += 4) {
        float2 x0 = __half22float2(__ldcs(&base[(size_t)r * (NC / 2)]));
        float2 x1 = __half22float2(__ldcs(&base[(size_t)(r + 1) * (NC / 2)]));
        float2 x2 = __half22float2(__ldcs(&base[(size_t)(r + 2) * (NC / 2)]));
        float2 x3 = __half22float2(__ldcs(&base[(size_t)(r + 3) * (NC / 2)]));
        a0.x += x0.x; a0.y += x0.y; a1.x += x1.x; a1.y += x1.y;
        a2.x += x2.x; a2.y += x2.y; a3.x += x3.x; a3.y += x3.y;
    }
    for (; r < n; r++) {
        float2 x0 = __half22float2(__ldcs(&base[(size_t)r * (NC / 2)]));
        a0.x += x0.x; a0.y += x0.y;
    }
    float invn = (n > 0) ? 1.f / (float)n : 0.f;
    float sx = (a0.x + a1.x) + (a2.x + a3.x);
    float sy = (a0.y + a1.y) + (a2.y + a3.y);
    ((__half2*)g_spfh)[((size_t)b * NSP + s) * (NC / 2) + t] =
        __floats2half2_rn(sx * invn, sy * invn);
}

// ---------------- fp16 mma GEMM (used for gemm1 only) ---------------------------
// flags: bit2 transposed fp16 out (C[n][m])
#define GM_BM 64
#define GM_BN 64
#define GM_BK 32
__global__ __launch_bounds__(128) void mma_gemm(
    const __half* __restrict__ A, int lda, size_t sA,
    const __half* __restrict__ B, int ldb, size_t sB,
    void* __restrict__ Cv, int ldc, size_t sC,
    int K, const float* __restrict__ bias, int flags)
{
    __shared__ __half As[GM_BM][GM_BK + 8];
    __shared__ __half Bs[GM_BN][GM_BK + 8];
    int b = blockIdx.z;
    A += (size_t)b * sA;
    B += (size_t)b * sB;
    int m0 = blockIdx.y * GM_BM, n0 = blockIdx.x * GM_BN;
    int tid = threadIdx.x, w = tid >> 5, lane = tid & 31;
    int wm = (w >> 1) * 32, wn = (w & 1) * 32;
    float acc[2][4][4];
    #pragma unroll
    for (int i = 0; i < 2; i++)
        #pragma unroll
        for (int j = 0; j < 4; j++)
            #pragma unroll
            for (int q = 0; q < 4; q++) acc[i][j][q] = 0.f;

    int r8 = lane & 7, grp = lane >> 3;
    for (int k0 = 0; k0 < K; k0 += GM_BK) {
        int rr = tid >> 1, oo = (tid & 1) * 16;
        {
            const __half* pa = A + (size_t)(m0 + rr) * lda + k0 + oo;
            *(uint4*)&As[rr][oo]     = *(const uint4*)pa;
            *(uint4*)&As[rr][oo + 8] = *(const uint4*)(pa + 8);
            const __half* pb = B + (size_t)(n0 + rr) * ldb + k0 + oo;
            *(uint4*)&Bs[rr][oo]     = *(const uint4*)pb;
            *(uint4*)&Bs[rr][oo + 8] = *(const uint4*)(pb + 8);
        }
        __syncthreads();
        #pragma unroll
        for (int kk = 0; kk < GM_BK; kk += 16) {
            unsigned af[2][4], bf[4][2];
            #pragma unroll
            for (int i = 0; i < 2; i++) {
                unsigned ad = sptr(&As[wm + i * 16 + r8 + ((grp & 1) << 3)][kk + ((grp & 2) << 2)]);
                ldsm4(af[i][0], af[i][1], af[i][2], af[i][3], ad);
            }
            #pragma unroll
            for (int jp = 0; jp < 2; jp++) {
                unsigned q0, q1, q2, q3;
                unsigned ad = sptr(&Bs[wn + jp * 16 + r8 + ((grp & 2) << 2)][kk + ((grp & 1) << 3)]);
                ldsm4(q0, q1, q2, q3, ad);
                bf[jp * 2][0] = q0;     bf[jp * 2][1] = q1;
                bf[jp * 2 + 1][0] = q2; bf[jp * 2 + 1][1] = q3;
            }
            #pragma unroll
            for (int i = 0; i < 2; i++)
                #pragma unroll
                for (int j = 0; j < 4; j++) mma16816(acc[i][j], af[i], bf[j]);
        }
        __syncthreads();
    }
    int rr = lane >> 2, cg = (lane & 3) * 2;
    #pragma unroll
    for (int i = 0; i < 2; i++) {
        int gm = m0 + wm + i * 16 + rr;
        #pragma unroll
        for (int j = 0; j < 4; j++) {
            int gn = n0 + wn + j * 8 + cg;
            float v0 = acc[i][j][0], v1 = acc[i][j][1];
            float v2 = acc[i][j][2], v3 = acc[i][j][3];
            if (flags & 4) {                       // transposed fp16 out: C[n][m]
                __half* C = (__half*)Cv + (size_t)b * sC;
                C[(size_t)gn * ldc + gm]           = __float2half(v0);
                C[(size_t)(gn + 1) * ldc + gm]     = __float2half(v1);
                C[(size_t)gn * ldc + gm + 8]       = __float2half(v2);
                C[(size_t)(gn + 1) * ldc + gm + 8] = __float2half(v3);
            } else {
                __half* C = (__half*)Cv + (size_t)b * sC;
                *(__half2*)(C + (size_t)gm * ldc + gn) = __floats2half2_rn(v0, v1);
                *(__half2*)(C + (size_t)(gm + 8) * ldc + gn) = __floats2half2_rn(v2, v3);
            }
        }
    }
}

// ---------------- adjacency GEMM: h1 = relu(D^-1/2 A D^-1/2 @ p + b1) ----------
__global__ __launch_bounds__(128) void adj_gemm(const float* __restrict__ bias) {
    __shared__ __half As[GM_BM][GM_BK + 8];
    __shared__ __half Bs[GM_BN][GM_BK + 8];
    __shared__ float sInv[NSP];
    int b = blockIdx.z;
    const unsigned char* A8 = g_adj + (size_t)b * NSP * NSP;
    const __half* B = g_pT + (size_t)b * HID * NSP;
    __half* C = g_h1 + (size_t)b * NSP * HID;
    int m0 = blockIdx.y * GM_BM, n0 = blockIdx.x * GM_BN;
    int tid = threadIdx.x, w = tid >> 5, lane = tid & 31;
    int wm = (w >> 1) * 32, wn = (w & 1) * 32;
    #pragma unroll
    for (int i = 0; i < NSP / 128; i++)
        sInv[tid + i * 128] = g_invdeg[b * NSP + tid + i * 128];
    __syncthreads();

    float acc[2][4][4];
    #pragma unroll
    for (int i = 0; i < 2; i++)
        #pragma unroll
        for (int j = 0; j < 4; j++)
            #pragma unroll
            for (int q = 0; q < 4; q++) acc[i][j][q] = 0.f;

    int r8 = lane & 7, grp = lane >> 3;
    for (int k0 = 0; k0 < NSP; k0 += GM_BK) {
        int rr = tid >> 1, oo = (tid & 1) * 16;
        {
            float im = sInv[m0 + rr];
            const unsigned* pa = (const unsigned*)(A8 + (size_t)(m0 + rr) * NSP + k0 + oo);
            __half hbuf[16];
            #pragma unroll
            for (int q = 0; q < 4; q++) {
                unsigned v = pa[q];
                #pragma unroll
                for (int e = 0; e < 4; e++) {
                    unsigned byte = (v >> (8 * e)) & 0xffu;
                    int kidx = k0 + oo + q * 4 + e;
                    hbuf[q * 4 + e] = byte ? __float2half(im * sInv[kidx]) : __half(0);
                }
            }
            *(uint4*)&As[rr][oo]     = *(uint4*)&hbuf[0];
            *(uint4*)&As[rr][oo + 8] = *(uint4*)&hbuf[8];
            const __half* pb = B + (size_t)(n0 + rr) * NSP + k0 + oo;
            *(uint4*)&Bs[rr][oo]     = *(const uint4*)pb;
            *(uint4*)&Bs[rr][oo + 8] = *(const uint4*)(pb + 8);
        }
        __syncthreads();
        #pragma unroll
        for (int kk = 0; kk < GM_BK; kk += 16) {
            unsigned af[2][4], bf[4][2];
            #pragma unroll
            for (int i = 0; i < 2; i++) {
                unsigned ad = sptr(&As[wm + i * 16 + r8 + ((grp & 1) << 3)][kk + ((grp & 2) << 2)]);
                ldsm4(af[i][0], af[i][1], af[i][2], af[i][3], ad);
            }
            #pragma unroll
            for (int jp = 0; jp < 2; jp++) {
                unsigned q0, q1, q2, q3;
                unsigned ad = sptr(&Bs[wn + jp * 16 + r8 + ((grp & 2) << 2)][kk + ((grp & 1) << 3)]);
                ldsm4(q0, q1, q2, q3, ad);
                bf[jp * 2][0] = q0;     bf[jp * 2][1] = q1;
                bf[jp * 2 + 1][0] = q2; bf[jp * 2 + 1][1] = q3;
            }
            #pragma unroll
            for (int i = 0; i < 2; i++)
                #pragma unroll
                for (int j = 0; j < 4; j++) mma16816(acc[i][j], af[i], bf[j]);
        }
        __syncthreads();
    }
    int rr = lane >> 2, cg = (lane & 3) * 2;
    #pragma unroll
    for (int i = 0; i < 2; i++) {
        int gm = m0 + wm + i * 16 + rr;
        #pragma unroll
        for (int j = 0; j < 4; j++) {
            int gn = n0 + wn + j * 8 + cg;
            float bx = bias[gn], by = bias[gn + 1];
            float v0 = fmaxf(acc[i][j][0] + bx, 0.f);
            float v1 = fmaxf(acc[i][j][1] + by, 0.f);
            float v2 = fmaxf(acc[i][j][2] + bx, 0.f);
            float v3 = fmaxf(acc[i][j][3] + by, 0.f);
            *(__half2*)(C + (size_t)gm * HID + gn) = __floats2half2_rn(v0, v1);
            *(__half2*)(C + (size_t)(gm + 8) * HID + gn) = __floats2half2_rn(v2, v3);
        }
    }
}

// ---------------- fused MLP: h2 = relu(h1@W2^T+b2); z = h2@Wp^T+bp; normalize --
__global__ __launch_bounds__(128) void mlp_kernel(const float* __restrict__ b2) {
    __shared__ __align__(16) unsigned char smraw[33792];
    __half (*As)[40]  = (__half(*)[40])smraw;                    // 5120 B
    __half (*Bs)[40]  = (__half(*)[40])(smraw + 5120);           // 10240 B
    __half (*H)[136]  = (__half(*)[136])(smraw + 15360);         // 17408 B
    float  (*Z)[132]  = (float(*)[132])smraw;                    // 33792 B (aliases all)
    int b = blockIdx.y, m0 = blockIdx.x * 64;
    int tid = threadIdx.x, w = tid >> 5, lane = tid & 31;
    int wm = (w >> 1) * 32, wn = (w & 1) * 64;
    int r8 = lane & 7, grp = lane >> 3;
    int rr2 = lane >> 2, cg = (lane & 3) * 2;
    const __half* A = g_h1 + (size_t)b * NSP * HID;

    // ---- phase 1: h2 tile = relu(h1 @ W2^T + b2) -> H smem
    {
        float acc[2][8][4];
        #pragma unroll
        for (int i = 0; i < 2; i++)
            #pragma unroll
            for (int j = 0; j < 8; j++)
                #pragma unroll
                for (int q = 0; q < 4; q++) acc[i][j][q] = 0.f;
        for (int k0 = 0; k0 < HID; k0 += 32) {
            {
                int rr = tid >> 1, oo = (tid & 1) * 16;
                const __half* pa = A + (size_t)(m0 + rr) * HID + k0 + oo;
                *(uint4*)&As[rr][oo]     = *(const uint4*)pa;
                *(uint4*)&As[rr][oo + 8] = *(const uint4*)(pa + 8);
                const __half* pb = g_w2h + (size_t)tid * HID + k0;
                *(uint4*)&Bs[tid][0]  = *(const uint4*)pb;
                *(uint4*)&Bs[tid][8]  = *(const uint4*)(pb + 8);
                *(uint4*)&Bs[tid][16] = *(const uint4*)(pb + 16);
                *(uint4*)&Bs[tid][24] = *(const uint4*)(pb + 24);
            }
            __syncthreads();
            #pragma unroll
            for (int kk = 0; kk < 32; kk += 16) {
                unsigned af[2][4], bf[8][2];
                #pragma unroll
                for (int i = 0; i < 2; i++) {
                    unsigned ad = sptr(&As[wm + i * 16 + r8 + ((grp & 1) << 3)][kk + ((grp & 2) << 2)]);
                    ldsm4(af[i][0], af[i][1], af[i][2], af[i][3], ad);
                }
                #pragma unroll
                for (int jp = 0; jp < 4; jp++) {
                    unsigned q0, q1, q2, q3;
                    unsigned ad = sptr(&Bs[wn + jp * 16 + r8 + ((grp & 2) << 2)][kk + ((grp & 1) << 3)]);
                    ldsm4(q0, q1, q2, q3, ad);
                    bf[jp * 2][0] = q0;     bf[jp * 2][1] = q1;
                    bf[jp * 2 + 1][0] = q2; bf[jp * 2 + 1][1] = q3;
                }
                #pragma unroll
                for (int i = 0; i < 2; i++)
                    #pragma unroll
                    for (int j = 0; j < 8; j++) mma16816(acc[i][j], af[i], bf[j]);
            }
            __syncthreads();
        }
        #pragma unroll
        for (int i = 0; i < 2; i++) {
            int gm = wm + i * 16 + rr2;
            #pragma unroll
            for (int j = 0; j < 8; j++) {
                int gn = wn + j * 8 + cg;
                float bx = b2[gn], by = b2[gn + 1];
                *(__half2*)&H[gm][gn] = __floats2half2_rn(
                    fmaxf(acc[i][j][0] + bx, 0.f), fmaxf(acc[i][j][1] + by, 0.f));
                *(__half2*)&H[gm + 8][gn] = __floats2half2_rn(
                    fmaxf(acc[i][j][2] + bx, 0.f), fmaxf(acc[i][j][3] + by, 0.f));
            }
        }
    }
    __syncthreads();
    // ---- phase 2: z tile = H @ Wph^T + bp -> Z smem (fp32)
    {
        float acc[2][8][4];
        #pragma unroll
        for (int i = 0; i < 2; i++)
            #pragma unroll
            for (int j = 0; j < 8; j++)
                #pragma unroll
                for (int q = 0; q < 4; q++) acc[i][j][q] = 0.f;
        for (int k0 = 0; k0 < HID; k0 += 32) {
            {
                const __half* pb = g_wph + (size_t)tid * HID + k0;
                *(uint4*)&Bs[tid][0]  = *(const uint4*)pb;
                *(uint4*)&Bs[tid][8]  = *(const uint4*)(pb + 8);
                *(uint4*)&Bs[tid][16] = *(const uint4*)(pb + 16);
                *(uint4*)&Bs[tid][24] = *(const uint4*)(pb + 24);
            }
            __syncthreads();
            #pragma unroll
            for (int kk = 0; kk < 32; kk += 16) {
                unsigned af[2][4], bf[8][2];
                #pragma unroll
                for (int i = 0; i < 2; i++) {
                    unsigned ad = sptr(&H[wm + i * 16 + r8 + ((grp & 1) << 3)][k0 + kk + ((grp & 2) << 2)]);
                    ldsm4(af[i][0], af[i][1], af[i][2], af[i][3], ad);
                }
                #pragma unroll
                for (int jp = 0; jp < 4; jp++) {
                    unsigned q0, q1, q2, q3;
                    unsigned ad = sptr(&Bs[wn + jp * 16 + r8 + ((grp & 2) << 2)][kk + ((grp & 1) << 3)]);
                    ldsm4(q0, q1, q2, q3, ad);
                    bf[jp * 2][0] = q0;     bf[jp * 2][1] = q1;
                    bf[jp * 2 + 1][0] = q2; bf[jp * 2 + 1][1] = q3;
                }
                #pragma unroll
                for (int i = 0; i < 2; i++)
                    #pragma unroll
                    for (int j = 0; j < 8; j++) mma16816(acc[i][j], af[i], bf[j]);
            }
            __syncthreads();
        }
        #pragma unroll
        for (int i = 0; i < 2; i++) {
            int gm = wm + i * 16 + rr2;
            #pragma unroll
            for (int j = 0; j < 8; j++) {
                int gn = wn + j * 8 + cg;
                float bx = g_bp[gn], by = g_bp[gn + 1];
                Z[gm][gn]         = acc[i][j][0] + bx;
                Z[gm][gn + 1]     = acc[i][j][1] + by;
                Z[gm + 8][gn]     = acc[i][j][2] + bx;
                Z[gm + 8][gn + 1] = acc[i][j][3] + by;
            }
        }
    }
    __syncthreads();
    // ---- normalize rows, emit fp16 z1h/z2h + fp32 diag
    for (int r = 0; r < 16; r++) {
        int row = w * 16 + r;
        float a0 = Z[row][lane], a1 = Z[row][lane + 32];
        float ss = a0 * a0 + a1 * a1;
        #pragma unroll
        for (int o = 16; o; o >>= 1) ss += __shfl_xor_sync(0xffffffffu, ss, o);
        float inv = rsqrtf(fmaxf(ss, 1e-30f));
        float a0n = a0 * inv, a1n = a1 * inv;
        float c0 = Z[row][64 + lane], c1 = Z[row][96 + lane];
        float ss2 = c0 * c0 + c1 * c1;
        #pragma unroll
        for (int o = 16; o; o >>= 1) ss2 += __shfl_xor_sync(0xffffffffu, ss2, o);
        float inv2 = rsqrtf(fmaxf(ss2, 1e-30f));
        float c0n = c0 * inv2, c1n = c1 * inv2;
        size_t base = ((size_t)b * NSP + m0 + row) * ODIM;
        g_z1h[base + lane]      = __float2half(a0n);
        g_z1h[base + lane + 32] = __float2half(a1n);
        g_z2h[base + lane]      = __float2half(c0n);
        g_z2h[base + lane + 32] = __float2half(c1n);
        float dd = a0n * c0n + a1n * c1n;
        #pragma unroll
        for (int o = 16; o; o >>= 1) dd += __shfl_xor_sync(0xffffffffu, dd, o);
        if (lane == 0) g_diag[b * NSP + m0 + row] = dd * INV_T;
    }
}

// ---------------- tensor-core sim + online logsumexp + loss --------------------
__global__ __launch_bounds__(128) void simlse_kernel(float* __restrict__ out) {
    __shared__ __half As[64][72];
    __shared__ __half Bs[64][72];
    __shared__ float pm[64][2], ps[64][2], sloss[64];
    int b = blockIdx.y, m0 = blockIdx.x * 64;
    int tid = threadIdx.x, w = tid >> 5, lane = tid & 31;
    int wm = (w >> 1) * 32, wn = (w & 1) * 32;
    int r8 = lane & 7, grp = lane >> 3;
    const __half* z1 = g_z1h + (size_t)b * NSP * ODIM;
    const __half* z2 = g_z2h + (size_t)b * NSP * ODIM;
    {
        int rr = tid >> 1, oo = (tid & 1) * 32;
        const __half* pa = z1 + (size_t)(m0 + rr) * ODIM + oo;
        *(uint4*)&As[rr][oo]      = *(const uint4*)pa;
        *(uint4*)&As[rr][oo + 8]  = *(const uint4*)(pa + 8);
        *(uint4*)&As[rr][oo + 16] = *(const uint4*)(pa + 16);
        *(uint4*)&As[rr][oo + 24] = *(const uint4*)(pa + 24);
    }
    float mrun[4], srun[4];
    #pragma unroll
    for (int i = 0; i < 4; i++) { mrun[i] = -1e30f; srun[i] = 0.f; }

    for (int n0 = 0; n0 < NSP; n0 += 64) {
        {
            int rr = tid >> 1, oo = (tid & 1) * 32;
            const __half* pb = z2 + (size_t)(n0 + rr) * ODIM + oo;
            *(uint4*)&Bs[rr][oo]      = *(const uint4*)pb;
            *(uint4*)&Bs[rr][oo + 8]  = *(const uint4*)(pb + 8);
            *(uint4*)&Bs[rr][oo + 16] = *(const uint4*)(pb + 16);
            *(uint4*)&Bs[rr][oo + 24] = *(const uint4*)(pb + 24);
        }
        __syncthreads();
        float acc[2][4][4];
        #pragma unroll
        for (int i = 0; i < 2; i++)
            #pragma unroll
            for (int j = 0; j < 4; j++)
                #pragma unroll
                for (int q = 0; q < 4; q++) acc[i][j][q] = 0.f;
        #pragma unroll
        for (int kk = 0; kk < ODIM; kk += 16) {
            unsigned af[2][4], bf[4][2];
            #pragma unroll
            for (int i = 0; i < 2; i++) {
                unsigned ad = sptr(&As[wm + i * 16 + r8 + ((grp & 1) << 3)][kk + ((grp & 2) << 2)]);
                ldsm4(af[i][0], af[i][1], af[i][2], af[i][3], ad);
            }
            #pragma unroll
            for (int jp = 0; jp < 2; jp++) {
                unsigned q0, q1, q2, q3;
                unsigned ad = sptr(&Bs[wn + jp * 16 + r8 + ((grp & 2) << 2)][kk + ((grp & 1) << 3)]);
                ldsm4(q0, q1, q2, q3, ad);
                bf[jp * 2][0] = q0;     bf[jp * 2][1] = q1;
                bf[jp * 2 + 1][0] = q2; bf[jp * 2 + 1][1] = q3;
            }
            #pragma unroll
            for (int i = 0; i < 2; i++)
                #pragma unroll
                for (int j = 0; j < 4; j++) mma16816(acc[i][j], af[i], bf[j]);
        }
        #pragma unroll
        for (int i = 0; i < 2; i++)
            #pragma unroll
            for (int j = 0; j < 4; j++)
                #pragma unroll
                for (int q = 0; q < 4; q++) {
                    float v = acc[i][j][q] * INV_T;
                    int slot = i * 2 + (q >> 1);
                    if (v > mrun[slot]) {
                        srun[slot] = srun[slot] * __expf(mrun[slot] - v) + 1.f;
                        mrun[slot] = v;
                    } else {
                        srun[slot] += __expf(v - mrun[slot]);
                    }
                }
        __syncthreads();
    }
    int rr2 = lane >> 2;
    #pragma unroll
    for (int slot = 0; slot < 4; slot++) {
        float m = mrun[slot], s = srun[slot];
        #pragma unroll
        for (int off = 1; off < 4; off <<= 1) {
            float m2 = __shfl_xor_sync(0xffffffffu, m, off);
            float s2 = __shfl_xor_sync(0xffffffffu, s, off);
            float mn = fmaxf(m, m2);
            s = s * __expf(m - mn) + s2 * __expf(m2 - mn);
            m = mn;
        }
        if ((lane & 3) == 0) {
            int row = wm + (slot >> 1) * 16 + rr2 + (slot & 1) * 8;
            pm[row][w & 1] = m;
            ps[row][w & 1] = s;
        }
    }
    __syncthreads();
    if (tid < 64) {
        float m0v = pm[tid][0], m1v = pm[tid][1];
        float mn = fmaxf(m0v, m1v);
        float s = ps[tid][0] * __expf(m0v - mn) + ps[tid][1] * __expf(m1v - mn);
        float lse = mn + logf(s);
        sloss[tid] = lse - g_diag[b * NSP + m0 + tid];
    }
    __syncthreads();
    if (tid == 0) {
        float sum = 0.f;
        #pragma unroll
        for (int i = 0; i < 64; i++) sum += sloss[i];
        atomicAdd(out, sum * (1.0f / (NBATCH * NSP)));
    }
}

// ---------------- host launcher -----------------------------------------------
static void* dvp(const void* sym) {
    void* p = nullptr;
    cudaGetSymbolAddress(&p, sym);
    return p;
}

extern "C" void kernel_launch(void* const* d_in, const int* in_sizes, int n_in,
                              void* d_out, int out_size) {
    const float* features = (const float*)d_in[0];
    const int*   spidx    = (const int*)d_in[1];
    const float* W1  = (const float*)d_in[2];
    const float* b1  = (const float*)d_in[3];
    const float* W2  = (const float*)d_in[4];
    const float* b2  = (const float*)d_in[5];
    const float* Wp1 = (const float*)d_in[6];
    const float* bp1 = (const float*)d_in[7];
    const float* Wp2 = (const float*)d_in[8];
    const float* bp2 = (const float*)d_in[9];
    float* out = (float*)d_out;

    __half* p_spfh = (__half*)dvp(g_spfh);
    __half* p_pT   = (__half*)dvp(g_pT);
    __half* p_w1h  = (__half*)dvp(g_w1h);

    prep_kernel<<<2048, 256>>>(out, W1, W2, Wp1, Wp2, bp1, bp2);
    count_adj_kernel<<<dim3(HW / 1024, NBATCH), 256>>>(spidx);
    scan_invdeg_kernel<<<NBATCH + (NBATCH * NSP) / 32, 1024>>>();
    transpose_kernel<<<dim3(HW / 64, NC / 64, NBATCH), 256>>>(features, spidx);
    segsum_kernel<<<dim3(NSP, NBATCH), 128>>>();
    // gemm1: pT[j][s] = (spfh @ W1^T)^T   (transposed fp16 out)
    mma_gemm<<<dim3(HID / GM_BN, NSP / GM_BM, NBATCH), 128>>>(
        p_spfh, NC, (size_t)NSP * NC,
        p_w1h, NC, 0,
        p_pT, NSP, (size_t)HID * NSP,
        NC, nullptr, 4);
    // gemm2: h1 = relu(adj_norm @ p + b1)
    adj_gemm<<<dim3(HID / GM_BN, NSP / GM_BM, NBATCH), 128>>>(b1);
    // fused mlp: h2, projections, row-normalize -> z1h/z2h/diag
    mlp_kernel<<<dim3(NSP / 64, NBATCH), 128>>>(b2);
    // fused tensor-core sim + lse + loss
    simlse_kernel<<<dim3(NSP / 64, NBATCH), 128>>>(out);
}